// round 12
// baseline (speedup 1.0000x reference)
#include <cuda_runtime.h>
#include <cuda_bf16.h>
#include <cuda_fp16.h>
#include <math.h>
#include <stdint.h>

#define T_  256
#define B_  64
#define D_  1024
#define H_  1024
#define DH_ 2048
#define NG_ 4096   /* 4 gates * H, packed n = j*4 + gate */
#define BH_ (B_ * H_)
#define M_  (T_ * B_)   /* 16384 */

// ---------------------------------------------------------------------------
// Device globals (scratch; no runtime allocation allowed)
// ---------------------------------------------------------------------------
__device__ __half g_wxf[(size_t)NG_ * D_];             // packed Wx fp16 (rows n=(j<<2)|gate)
__device__ __half g_whf[(size_t)NG_ * H_];             // packed Wh fp16 hi
__device__ __half g_wlf[(size_t)NG_ * H_];             // packed Wh fp16 lo
// X pre-swizzled chunk-major fp16: [t][c64 0..15][8192 B], off = SWZ(b*128+(k%64)*2)
__device__ __align__(128) char g_xf[(size_t)T_ * 16 * 8192];
// h double buffer, single fp16, pre-swizzled chunk-major: [buf][c64 0..15][8192 B]
__device__ __align__(128) char g_hf[2][16][8192];
__device__ unsigned g_bar;                             // grid barrier counter

#define HBUF_STRIDE_ 131072   /* 16*8192 */

// ---------------------------------------------------------------------------
// PTX helpers (compute_103-portable)
// ---------------------------------------------------------------------------
__device__ __forceinline__ uint32_t smem_u32(const void* p) {
    uint32_t a;
    asm("{ .reg .u64 t; cvta.to.shared.u64 t, %1; cvt.u32.u64 %0, t; }" : "=r"(a) : "l"(p));
    return a;
}
__device__ __forceinline__ void cp_async16(uint32_t smem, const void* g) {
    asm volatile("cp.async.cg.shared.global [%0], [%1], 16;" :: "r"(smem), "l"(g) : "memory");
}
#define CP_COMMIT() asm volatile("cp.async.commit_group;" ::: "memory")
#define CP_WAIT(n)  asm volatile("cp.async.wait_group %0;" :: "n"(n) : "memory")

__device__ __forceinline__ void cp_bulk(uint32_t dst, const void* src, uint32_t bytes,
                                        uint32_t mbar) {
    asm volatile("cp.async.bulk.shared::cta.global.mbarrier::complete_tx::bytes "
                 "[%0], [%1], %2, [%3];"
                 :: "r"(dst), "l"(src), "r"(bytes), "r"(mbar) : "memory");
}
#define MBARRIER_INIT(mbar, cnt) \
    asm volatile("mbarrier.init.shared.b64 [%0], %1;" :: "r"((uint32_t)(mbar)), "r"((uint32_t)(cnt)) : "memory")
#define MBARRIER_EXPECT_TX(mbar, bytes) \
    asm volatile("mbarrier.arrive.expect_tx.shared.b64 _, [%0], %1;" \
        :: "r"((uint32_t)(mbar)), "r"((uint32_t)(bytes)) : "memory")
#define MBARRIER_WAIT_PARITY(mbar, parity) do { \
    uint32_t _m = (uint32_t)(mbar); uint32_t _p = (uint32_t)(parity); uint32_t _d; \
    asm volatile("{\n\t.reg .pred p;\n\t" \
        "mbarrier.try_wait.parity.acquire.cta.shared::cta.b64 p, [%1], %2;\n\t" \
        "selp.b32 %0, 1, 0, p;\n\t}" : "=r"(_d) : "r"(_m), "r"(_p) : "memory"); \
    if (!_d) { \
        asm volatile("{\n\t.reg .pred P1;\n\tWL_%=:\n\t" \
            "mbarrier.try_wait.parity.acquire.cta.shared::cta.b64 P1, [%0], %1, 0x989680;\n\t" \
            "@P1 bra.uni WD_%=;\n\tbra.uni WL_%=;\n\tWD_%=:\n\t}" \
            :: "r"(_m), "r"(_p) : "memory"); \
    } } while (0)

__device__ __forceinline__ void ldsm_x4(uint32_t& r0, uint32_t& r1, uint32_t& r2, uint32_t& r3,
                                        uint32_t addr) {
    asm volatile("ldmatrix.sync.aligned.m8n8.x4.shared.b16 {%0,%1,%2,%3}, [%4];"
                 : "=r"(r0), "=r"(r1), "=r"(r2), "=r"(r3) : "r"(addr));
}
__device__ __forceinline__ void mma_f16(float* c,
                                        uint32_t a0, uint32_t a1, uint32_t a2, uint32_t a3,
                                        uint32_t b0, uint32_t b1) {
    asm volatile("mma.sync.aligned.m16n8k16.row.col.f32.f16.f16.f32 "
                 "{%0,%1,%2,%3}, {%4,%5,%6,%7}, {%8,%9}, {%0,%1,%2,%3};"
                 : "+f"(c[0]), "+f"(c[1]), "+f"(c[2]), "+f"(c[3])
                 : "r"(a0), "r"(a1), "r"(a2), "r"(a3), "r"(b0), "r"(b1));
}
#define SWZ(off) ((off) ^ (((off) >> 3) & 0x70))

__device__ __forceinline__ float sigf(float x) { return 1.0f / (1.0f + __expf(-x)); }
__device__ __forceinline__ float tanh_fast(float x) {
    float a = fabsf(x);
    float e = __expf(-2.0f * a);
    float t = (1.0f - e) / (1.0f + e);
    return copysignf(t, x);
}

// ---------------------------------------------------------------------------
// Phase 0a: split Wh (h-part) into packed fp16 hi/lo. Row n=(j<<2)|gate.
// ---------------------------------------------------------------------------
__global__ __launch_bounds__(256) void conv_w(
    const float* __restrict__ Wf, const float* __restrict__ Wi,
    const float* __restrict__ Wu, const float* __restrict__ Wo,
    __half* __restrict__ hi, __half* __restrict__ lo)
{
    size_t idx = (size_t)blockIdx.x * 256 + threadIdx.x;   // over NG_*H_
    int n = (int)(idx >> 10);
    int k = (int)(idx & 1023);
    int j = n >> 2, gate = n & 3;
    const float* W = (gate == 0) ? Wf : (gate == 1) ? Wi : (gate == 2) ? Wu : Wo;
    float w = W[(size_t)j * DH_ + D_ + k];
    __half h16 = __float2half(w);
    hi[idx] = h16;
    lo[idx] = __float2half(w - __half2float(h16));
}

// Phase 0b: pack Wx (x-part) single fp16. Row n=(j<<2)|gate.
__global__ __launch_bounds__(256) void conv_wx(
    const float* __restrict__ Wf, const float* __restrict__ Wi,
    const float* __restrict__ Wu, const float* __restrict__ Wo,
    __half* __restrict__ wq)
{
    size_t idx = (size_t)blockIdx.x * 256 + threadIdx.x;   // over NG_*D_
    int n = (int)(idx >> 10);
    int k = (int)(idx & 1023);
    int j = n >> 2, gate = n & 3;
    const float* W = (gate == 0) ? Wf : (gate == 1) ? Wi : (gate == 2) ? Wu : Wo;
    wq[idx] = __float2half(W[(size_t)j * DH_ + k]);
}

// Phase 0c: X -> fp16, pre-swizzled chunk-major [t][c64][SWZ(b*128+(k%64)*2)].
// Each thread converts 8 consecutive k (one 16B store).
__global__ __launch_bounds__(256) void conv_x(
    const float* __restrict__ X, char* __restrict__ Xq)
{
    size_t g = (size_t)blockIdx.x * 256 + threadIdx.x;   // over M_*D_/8
    int m  = (int)(g >> 7);          // 0..16383
    int k8 = (int)(g & 127);
    int k  = k8 * 8;
    int t  = m >> 6;
    int b  = m & 63;
    int c64 = k >> 6;

    const float* src = X + ((size_t)m << 10) + k;
    float4 v0 = *(const float4*)(src);
    float4 v1 = *(const float4*)(src + 4);
    __half h[8];
    h[0] = __float2half(v0.x); h[1] = __float2half(v0.y);
    h[2] = __float2half(v0.z); h[3] = __float2half(v0.w);
    h[4] = __float2half(v1.x); h[5] = __float2half(v1.y);
    h[6] = __float2half(v1.z); h[7] = __float2half(v1.w);

    uint32_t off = SWZ((uint32_t)(b * 128 + (k & 63) * 2));
    char* dst = Xq + ((size_t)(t * 16 + c64)) * 8192 + off;
    *(uint4*)dst = *(uint4*)h;
}

// ---------------------------------------------------------------------------
// Phase 2 (now the only GEMM phase): persistent fused QLSTM.
// Per CTA: 32 packed gate rows, resident W = [Wx | Wh_hi | Wh_lo] fp16 (192 KB).
// Per step: 32 streamed A chunks (16 X + 16 h, 8 KB each) through a 2-stage
// 16 KB pipeline (R7 control flow). z = X@Wx^T + h@(Wh_hi+Wh_lo)^T in fp32
// regs; fused bias+cos+LSTM epilogue; h fp16 out. Grid barrier polled ONLY by
// tid0 at the X->h transition, hidden behind the X-half MMAs.
// SMEM: WX 64K @0 | WHH 64K @64K | WHL 64K @128K | A 2x16K @192K (Zs overlays)
// ---------------------------------------------------------------------------
#define WX_      0
#define WHH_     65536
#define WHL_     131072
#define AST_(s)  (196608 + (s) * 16384)
#define ZS_OFF_  196608
#define SMEM_DYN_ 229376

__global__ __launch_bounds__(256) void lstm_persist(
    const char* __restrict__ Xq,       // g_xf
    const __half* __restrict__ Wxf,
    const __half* __restrict__ Whf,
    const __half* __restrict__ Wlf,
    char* __restrict__ Hf,             // g_hf base
    const float* __restrict__ bf, const float* __restrict__ bi,
    const float* __restrict__ bu, const float* __restrict__ bo,
    const float* __restrict__ gbf, const float* __restrict__ gbi,
    const float* __restrict__ gbu, const float* __restrict__ gbo,
    float* __restrict__ out,           // [T][B][H]
    float* __restrict__ hc_tail)       // null or [hx|cx]
{
    extern __shared__ __align__(1024) char sm[];
    __shared__ float s_b[32];
    __shared__ float s_gb[32];
    __shared__ __align__(8) uint64_t s_mbar[2];

    const uint32_t sbase = smem_u32(sm);
    const int tid  = threadIdx.x;
    const int wid  = tid >> 5;
    const int lane = tid & 31;
    const int bx   = blockIdx.x;
    const int j0   = bx * 8;

    if (tid < 32) {
        int gate = tid >> 3, jl = tid & 7;
        const float* gp = (gate == 0) ? gbf : (gate == 1) ? gbi : (gate == 2) ? gbu : gbo;
        const float* bp = (gate == 0) ? bf  : (gate == 1) ? bi  : (gate == 2) ? bu  : bo;
        s_gb[tid] = gp[j0 + jl];
        s_b[tid]  = bp[j0 + jl];
    }
    if (tid == 0) {
        MBARRIER_INIT(smem_u32(&s_mbar[0]), 1);
        MBARRIER_INIT(smem_u32(&s_mbar[1]), 1);
    }

    // ---- resident weights once: Wx, Wh_hi, Wh_lo (32 rows x 1024 fp16 each) ----
    {
        const char* wx8 = (const char*)(Wxf + (size_t)bx * 32 * D_);
        const char* wh8 = (const char*)(Whf + (size_t)bx * 32 * H_);
        const char* wl8 = (const char*)(Wlf + (size_t)bx * 32 * H_);
        for (int i = tid; i < 4096; i += 256) {
            int c  = i >> 8;
            int r  = (i >> 3) & 31;
            int cg = i & 7;
            size_t goff = (size_t)r * 2048 + (size_t)c * 128 + cg * 16;
            uint32_t soff = (uint32_t)c * 4096 + SWZ((uint32_t)(r * 128 + cg * 16));
            cp_async16(sbase + WX_  + soff, wx8 + goff);
            cp_async16(sbase + WHH_ + soff, wh8 + goff);
            cp_async16(sbase + WHL_ + soff, wl8 + goff);
        }
        CP_COMMIT(); CP_WAIT(0);
        __syncthreads();
    }

    const int wm = wid & 3;              // 16 batch rows
    const int wn = wid >> 2;             // 16 packed cols
    const int m0 = wm * 16;

    const uint32_t a_r  = (uint32_t)(m0 + (lane & 15));
    const uint32_t a_kb = (uint32_t)((lane >> 4) << 3);
    const uint32_t b_nt = (uint32_t)((lane >> 3) >> 1);
    const uint32_t b_kb = (uint32_t)(((lane >> 3) & 1) * 8);
    const uint32_t b_r  = (uint32_t)(lane & 7);
    const uint32_t b_row = (uint32_t)(wn * 16) + b_nt * 8 + b_r;

    const uint32_t mb0 = smem_u32(&s_mbar[0]);
    const uint32_t mb1 = smem_u32(&s_mbar[1]);

    int ph[2] = {0, 0};
    float c_reg[2] = {0.f, 0.f};

    const int hc64 = j0 >> 6;          // this CTA's produced h chunk
    const int kcb  = j0 & 63;

    for (int t = 0; t < T_; t++) {
        const char* xsrc = Xq + (size_t)t * HBUF_STRIDE_;
        const char* hin  = Hf + (size_t)(t & 1) * HBUF_STRIDE_;
        char* hout = Hf + (size_t)((t + 1) & 1) * HBUF_STRIDE_;

        // prologue: first two X chunk-pairs (no dependency on h / barrier)
        if (tid == 0) {
            asm volatile("fence.proxy.async;" ::: "memory");
#pragma unroll
            for (int pc = 0; pc < 2; pc++) {
                uint32_t mb = pc ? mb1 : mb0;
                MBARRIER_EXPECT_TX(mb, 16384);
#pragma unroll
                for (int sub = 0; sub < 2; sub++) {
                    int q = pc * 2 + sub;    // X chunks 0..3
                    cp_bulk(sbase + AST_(pc) + sub * 8192,
                            xsrc + (size_t)q * 8192, 8192, mb);
                }
            }
        }

        float acc[2][4];
#pragma unroll
        for (int nt = 0; nt < 2; nt++)
#pragma unroll
            for (int i = 0; i < 4; i++) acc[nt][i] = 0.0f;

        for (int ch = 0; ch < 16; ch++) {
            const int s = ch & 1;
            MBARRIER_WAIT_PARITY(s ? mb1 : mb0, ph[s]);
            ph[s] ^= 1;

#pragma unroll
            for (int sub = 0; sub < 2; sub++) {
                const int q   = ch * 2 + sub;
                const int c64 = q & 15;
                const uint32_t Aa = sbase + AST_(s) + sub * 8192;

                if (q < 16) {
                    // X half: single product with Wx
                    const uint32_t Bx = sbase + WX_ + (uint32_t)c64 * 4096;
#pragma unroll
                    for (int ks = 0; ks < 4; ks++) {
                        uint32_t aoff = SWZ((a_r << 7) + (ks * 16 + a_kb) * 2);
                        uint32_t a0, a1, a2, a3;
                        ldsm_x4(a0, a1, a2, a3, Aa + aoff);
                        uint32_t boff = SWZ((b_row << 7) + (ks * 16 + b_kb) * 2);
                        uint32_t b0, b1, b2, b3;
                        ldsm_x4(b0, b1, b2, b3, Bx + boff);
                        mma_f16(acc[0], a0, a1, a2, a3, b0, b1);
                        mma_f16(acc[1], a0, a1, a2, a3, b2, b3);
                    }
                } else {
                    // h half: two products with Wh_hi + Wh_lo
                    const uint32_t Bh = sbase + WHH_ + (uint32_t)c64 * 4096;
                    const uint32_t Bl = sbase + WHL_ + (uint32_t)c64 * 4096;
#pragma unroll
                    for (int ks = 0; ks < 4; ks++) {
                        uint32_t aoff = SWZ((a_r << 7) + (ks * 16 + a_kb) * 2);
                        uint32_t a0, a1, a2, a3;
                        ldsm_x4(a0, a1, a2, a3, Aa + aoff);
                        uint32_t boff = SWZ((b_row << 7) + (ks * 16 + b_kb) * 2);
                        uint32_t bh0, bh1, bh2, bh3, bl0, bl1, bl2, bl3;
                        ldsm_x4(bh0, bh1, bh2, bh3, Bh + boff);
                        ldsm_x4(bl0, bl1, bl2, bl3, Bl + boff);
                        mma_f16(acc[0], a0, a1, a2, a3, bh0, bh1);
                        mma_f16(acc[0], a0, a1, a2, a3, bl0, bl1);
                        mma_f16(acc[1], a0, a1, a2, a3, bh2, bh3);
                        mma_f16(acc[1], a0, a1, a2, a3, bl2, bl3);
                    }
                }
            }
            __syncthreads();

            // refill stage s with chunk pair ch+2 (q = 2ch+4, 2ch+5)
            if (ch + 2 < 16 && tid == 0) {
                // crossing into h chunks (q >= 16): wait for all producers of step t-1
                if (ch == 6 && t > 0) {
                    unsigned target = (unsigned)t * 128u;
                    unsigned v;
                    do {
                        asm volatile("ld.acquire.gpu.u32 %0, [%1];" : "=r"(v) : "l"(&g_bar) : "memory");
                    } while (v < target);
                }
                asm volatile("fence.proxy.async;" ::: "memory");
                uint32_t mb = s ? mb1 : mb0;
                MBARRIER_EXPECT_TX(mb, 16384);
#pragma unroll
                for (int sub = 0; sub < 2; sub++) {
                    int q = (ch + 2) * 2 + sub;
                    const char* src = (q < 16) ? xsrc + (size_t)q * 8192
                                               : hin + (size_t)(q - 16) * 8192;
                    cp_bulk(sbase + AST_(s) + sub * 8192, src, 8192, mb);
                }
            }
        }

        // stage accumulators to SMEM (overlay A stage 0)
        float* Zs = (float*)(sm + ZS_OFF_);
        {
            const int g  = lane >> 2;
            const int tg = lane & 3;
#pragma unroll
            for (int nt = 0; nt < 2; nt++) {
                int n = wn * 16 + nt * 8 + tg * 2;
                Zs[(m0 + g)     * 32 + n]     = acc[nt][0];
                Zs[(m0 + g)     * 32 + n + 1] = acc[nt][1];
                Zs[(m0 + g + 8) * 32 + n]     = acc[nt][2];
                Zs[(m0 + g + 8) * 32 + n + 1] = acc[nt][3];
            }
        }
        __syncthreads();

        // fused LSTM epilogue: 512 (b, jl) pairs, 2 per thread, c in registers
        float* out_t = out + (size_t)t * BH_;
        char* hout_c = hout + (size_t)hc64 * 8192;
#pragma unroll
        for (int p0 = 0; p0 < 2; p0++) {
            int p  = tid + p0 * 256;
            int b  = p >> 3;
            int jl = p & 7;
            float4 zh = *(const float4*)&Zs[b * 32 + jl * 4];

            float f  = sigf(__cosf(zh.x + s_b[0 * 8 + jl]) + s_gb[0 * 8 + jl]);
            float ii = sigf(__cosf(zh.y + s_b[1 * 8 + jl]) + s_gb[1 * 8 + jl]);
            float g  = tanh_fast(__cosf(zh.z + s_b[2 * 8 + jl]) + s_gb[2 * 8 + jl]);
            float o  = sigf(__cosf(zh.w + s_b[3 * 8 + jl]) + s_gb[3 * 8 + jl]);

            float c = f * c_reg[p0] + ii * g;
            c_reg[p0] = c;
            float h = o * tanh_fast(c);

            size_t idx = (size_t)b * H_ + j0 + jl;
            out_t[idx] = h;

            uint32_t hoff = SWZ((uint32_t)(b * 128 + (kcb + jl) * 2));
            *(__half*)(hout_c + hoff) = __float2half(h);

            if (hc_tail && t == T_ - 1) {
                hc_tail[idx] = h;
                hc_tail[(size_t)BH_ + idx] = c;
            }
        }

        // publish this step's h (workers continue into next step's X half)
        if (t + 1 < T_) {
            __syncthreads();
            if (tid == 0) {
                asm volatile("red.release.gpu.add.u32 [%0], 1;" :: "l"(&g_bar) : "memory");
            }
        }
    }
}

// ---------------------------------------------------------------------------
extern "C" void kernel_launch(void* const* d_in, const int* in_sizes, int n_in,
                              void* d_out, int out_size)
{
    const float* X   = (const float*)d_in[0];
    const float* Wf  = (const float*)d_in[1];
    const float* bf  = (const float*)d_in[2];
    const float* gbf = (const float*)d_in[3];
    const float* Wi  = (const float*)d_in[4];
    const float* bi  = (const float*)d_in[5];
    const float* gbi = (const float*)d_in[6];
    const float* Wu  = (const float*)d_in[7];
    const float* bu  = (const float*)d_in[8];
    const float* gbu = (const float*)d_in[9];
    const float* Wo  = (const float*)d_in[10];
    const float* bo  = (const float*)d_in[11];
    const float* gbo = (const float*)d_in[12];

    float* out = (float*)d_out;

    __half *p_wxf, *p_whf, *p_wlf;
    char *p_xf, *p_hf;
    unsigned* p_bar;
    cudaGetSymbolAddress((void**)&p_wxf, g_wxf);
    cudaGetSymbolAddress((void**)&p_whf, g_whf);
    cudaGetSymbolAddress((void**)&p_wlf, g_wlf);
    cudaGetSymbolAddress((void**)&p_xf,  g_xf);
    cudaGetSymbolAddress((void**)&p_hf,  g_hf);
    cudaGetSymbolAddress((void**)&p_bar, g_bar);

    cudaFuncSetAttribute(lstm_persist, cudaFuncAttributeMaxDynamicSharedMemorySize, SMEM_DYN_);

    // reset initial h buffer (parity 0) and the barrier counter
    cudaMemsetAsync(p_hf, 0, HBUF_STRIDE_);
    cudaMemsetAsync(p_bar, 0, sizeof(unsigned));

    // Phase 0: weight/input conversion
    conv_w<<<(NG_ * H_) / 256, 256>>>(Wf, Wi, Wu, Wo, p_whf, p_wlf);
    conv_wx<<<(NG_ * D_) / 256, 256>>>(Wf, Wi, Wu, Wo, p_wxf);
    conv_x<<<(M_ * D_ / 8) / 256, 256>>>(X, p_xf);

    // Single persistent kernel: x-projection + recurrence + activations fused
    const size_t TBH = (size_t)T_ * B_ * H_;
    const bool tails = out_size >= (int)(TBH + 2 * (size_t)BH_);
    lstm_persist<<<128, 256, SMEM_DYN_>>>(
        p_xf, p_wxf, p_whf, p_wlf, p_hf,
        bf, bi, bu, bo,
        gbf, gbi, gbu, gbo,
        out, tails ? out + TBH : nullptr);
}

// round 13
// speedup vs baseline: 1.8166x; 1.8166x over previous
#include <cuda_runtime.h>
#include <cuda_bf16.h>
#include <cuda_fp16.h>
#include <math.h>
#include <stdint.h>

#define T_  256
#define B_  64
#define D_  1024
#define H_  1024
#define DH_ 2048
#define NG_ 4096   /* 4 gates * H, packed n = j*4 + gate */
#define BH_ (B_ * H_)
#define M_  (T_ * B_)   /* 16384 */

// ---------------------------------------------------------------------------
// Device globals (scratch; no runtime allocation allowed)
// ---------------------------------------------------------------------------
// Zx in per-CTA slabs: [t][grp=0..127][64 b x 32 cols] fp32, slab = 8KB contiguous
__device__ float g_zx[(size_t)T_ * B_ * NG_];
__device__ __half g_whf[(size_t)NG_ * H_];             // packed Wh single fp16
__device__ __half g_wxf[(size_t)NG_ * D_];             // packed Wx single fp16
__device__ __half g_xf[(size_t)M_ * D_];               // X single fp16
// h double buffer, single fp16, pre-swizzled chunk-major: [buf][c64 0..15][8192 B]
// within chunk: byte off = SWZ(b*128 + (k%64)*2)
__device__ __align__(128) char g_hf[2][16][8192];
__device__ unsigned g_bar;                             // grid barrier counter

#define HBUF_STRIDE_ 131072   /* 16*8192 */

// ---------------------------------------------------------------------------
// PTX helpers (compute_103-portable)
// ---------------------------------------------------------------------------
__device__ __forceinline__ uint32_t smem_u32(const void* p) {
    uint32_t a;
    asm("{ .reg .u64 t; cvta.to.shared.u64 t, %1; cvt.u32.u64 %0, t; }" : "=r"(a) : "l"(p));
    return a;
}
__device__ __forceinline__ void cp_async16(uint32_t smem, const void* g) {
    asm volatile("cp.async.cg.shared.global [%0], [%1], 16;" :: "r"(smem), "l"(g) : "memory");
}
#define CP_COMMIT() asm volatile("cp.async.commit_group;" ::: "memory")
#define CP_WAIT(n)  asm volatile("cp.async.wait_group %0;" :: "n"(n) : "memory")

// 1D bulk copy global->shared with mbarrier completion (sm_90+, portable)
__device__ __forceinline__ void cp_bulk(uint32_t dst, const void* src, uint32_t bytes,
                                        uint32_t mbar) {
    asm volatile("cp.async.bulk.shared::cta.global.mbarrier::complete_tx::bytes "
                 "[%0], [%1], %2, [%3];"
                 :: "r"(dst), "l"(src), "r"(bytes), "r"(mbar) : "memory");
}
#define MBARRIER_INIT(mbar, cnt) \
    asm volatile("mbarrier.init.shared.b64 [%0], %1;" :: "r"((uint32_t)(mbar)), "r"((uint32_t)(cnt)) : "memory")
#define MBARRIER_EXPECT_TX(mbar, bytes) \
    asm volatile("mbarrier.arrive.expect_tx.shared.b64 _, [%0], %1;" \
        :: "r"((uint32_t)(mbar)), "r"((uint32_t)(bytes)) : "memory")
#define MBARRIER_WAIT_PARITY(mbar, parity) do { \
    uint32_t _m = (uint32_t)(mbar); uint32_t _p = (uint32_t)(parity); uint32_t _d; \
    asm volatile("{\n\t.reg .pred p;\n\t" \
        "mbarrier.try_wait.parity.acquire.cta.shared::cta.b64 p, [%1], %2;\n\t" \
        "selp.b32 %0, 1, 0, p;\n\t}" : "=r"(_d) : "r"(_m), "r"(_p) : "memory"); \
    if (!_d) { \
        asm volatile("{\n\t.reg .pred P1;\n\tWL_%=:\n\t" \
            "mbarrier.try_wait.parity.acquire.cta.shared::cta.b64 P1, [%0], %1, 0x989680;\n\t" \
            "@P1 bra.uni WD_%=;\n\tbra.uni WL_%=;\n\tWD_%=:\n\t}" \
            :: "r"(_m), "r"(_p) : "memory"); \
    } } while (0)

__device__ __forceinline__ void ldsm_x4(uint32_t& r0, uint32_t& r1, uint32_t& r2, uint32_t& r3,
                                        uint32_t addr) {
    asm volatile("ldmatrix.sync.aligned.m8n8.x4.shared.b16 {%0,%1,%2,%3}, [%4];"
                 : "=r"(r0), "=r"(r1), "=r"(r2), "=r"(r3) : "r"(addr));
}
__device__ __forceinline__ void mma_f16(float* c,
                                        uint32_t a0, uint32_t a1, uint32_t a2, uint32_t a3,
                                        uint32_t b0, uint32_t b1) {
    asm volatile("mma.sync.aligned.m16n8k16.row.col.f32.f16.f16.f32 "
                 "{%0,%1,%2,%3}, {%4,%5,%6,%7}, {%8,%9}, {%0,%1,%2,%3};"
                 : "+f"(c[0]), "+f"(c[1]), "+f"(c[2]), "+f"(c[3])
                 : "r"(a0), "r"(a1), "r"(a2), "r"(a3), "r"(b0), "r"(b1));
}
#define SWZ(off) ((off) ^ (((off) >> 3) & 0x70))

__device__ __forceinline__ float sigf(float x) { return 1.0f / (1.0f + __expf(-x)); }
__device__ __forceinline__ float tanh_fast(float x) {
    float a = fabsf(x);
    float e = __expf(-2.0f * a);
    float t = (1.0f - e) / (1.0f + e);
    return copysignf(t, x);
}

// ---------------------------------------------------------------------------
// Phase 0a: pack Wh (h-part) single fp16. Row n=(j<<2)|gate.
// ---------------------------------------------------------------------------
__global__ __launch_bounds__(256) void conv_w(
    const float* __restrict__ Wf, const float* __restrict__ Wi,
    const float* __restrict__ Wu, const float* __restrict__ Wo,
    __half* __restrict__ wq)
{
    size_t idx = (size_t)blockIdx.x * 256 + threadIdx.x;   // over NG_*H_
    int n = (int)(idx >> 10);
    int k = (int)(idx & 1023);
    int j = n >> 2, gate = n & 3;
    const float* W = (gate == 0) ? Wf : (gate == 1) ? Wi : (gate == 2) ? Wu : Wo;
    wq[idx] = __float2half(W[(size_t)j * DH_ + D_ + k]);
}

// Phase 0b: pack Wx (x-part) single fp16. Row n=(j<<2)|gate.
__global__ __launch_bounds__(256) void conv_wx(
    const float* __restrict__ Wf, const float* __restrict__ Wi,
    const float* __restrict__ Wu, const float* __restrict__ Wo,
    __half* __restrict__ wq)
{
    size_t idx = (size_t)blockIdx.x * 256 + threadIdx.x;   // over NG_*D_
    int n = (int)(idx >> 10);
    int k = (int)(idx & 1023);
    int j = n >> 2, gate = n & 3;
    const float* W = (gate == 0) ? Wf : (gate == 1) ? Wi : (gate == 2) ? Wu : Wo;
    wq[idx] = __float2half(W[(size_t)j * DH_ + k]);
}

// Phase 0c: X single fp16.
__global__ __launch_bounds__(256) void conv_x(
    const float* __restrict__ X, __half* __restrict__ xq)
{
    size_t idx = (size_t)blockIdx.x * 256 + threadIdx.x;   // over M_*D_
    xq[idx] = __float2half(X[idx]);
}

// ---------------------------------------------------------------------------
// Phase 1: input projection on tensor cores, single fp16 (R11-proven).
// Z(M x NG, packed) = X @ Wx^T + bias, fp32 out, per-CTA slab layout:
//   zidx(m,n) = ((m>>6)*128 + (n>>5))*2048 + (m&63)*32 + (n&31)
// ---------------------------------------------------------------------------
#define FA_(s)   ((s) * 32768)
#define FB_(s)   ((s) * 32768 + 16384)
#define GSMEM_   65536

__global__ __launch_bounds__(256) void gemm_tc(
    const __half* __restrict__ Xq,
    const __half* __restrict__ Wq,
    const float* __restrict__ bf, const float* __restrict__ bi,
    const float* __restrict__ bu, const float* __restrict__ bo,
    float* __restrict__ Z)
{
    extern __shared__ __align__(1024) char sm[];
    __shared__ float s_bias[128];

    const uint32_t sbase = smem_u32(sm);
    const int tid  = threadIdx.x;
    const int wid  = tid >> 5;
    const int lane = tid & 31;
    const int n0   = blockIdx.x * 128;   // packed col base
    const int m0   = blockIdx.y * 128;

    const int wm = wid & 1;              // M half (64 rows)
    const int wn = wid >> 1;             // N quarter (32 cols)

    if (tid < 128) {
        int n = n0 + tid, gate = n & 3, j = n >> 2;
        const float* Ba = (gate == 0) ? bf : (gate == 1) ? bi : (gate == 2) ? bu : bo;
        s_bias[tid] = Ba[j];
    }

    const char* x8 = (const char*)(Xq + (size_t)m0 * D_);
    const char* w8 = (const char*)(Wq + (size_t)n0 * D_);

    auto load_chunk = [&](int ch, int s) {
#pragma unroll
        for (int r4 = 0; r4 < 4; r4++) {
            int idx = tid + r4 * 256;          // 1024 slots = 128 rows x 8 cg
            int row = idx >> 3, cg = idx & 7;
            size_t goff = (size_t)row * 2048 + (size_t)ch * 128 + cg * 16;
            uint32_t soff = SWZ((uint32_t)(row * 128 + cg * 16));
            cp_async16(sbase + FA_(s) + soff, x8 + goff);
            cp_async16(sbase + FB_(s) + soff, w8 + goff);
        }
    };

    float acc[4][4][4];
#pragma unroll
    for (int mt = 0; mt < 4; mt++)
#pragma unroll
        for (int nt = 0; nt < 4; nt++)
#pragma unroll
            for (int i = 0; i < 4; i++) acc[mt][nt][i] = 0.0f;

    const uint32_t a_kb = (uint32_t)((lane >> 4) << 3);
    const uint32_t b_nt = (uint32_t)((lane >> 3) >> 1);
    const uint32_t b_kb = (uint32_t)(((lane >> 3) & 1) * 8);
    const uint32_t b_r  = (uint32_t)(lane & 7);

    load_chunk(0, 0);
    CP_COMMIT();

    for (int ch = 0; ch < 16; ch++) {
        const int s = ch & 1;
        if (ch + 1 < 16) {
            load_chunk(ch + 1, s ^ 1);
            CP_COMMIT();
            CP_WAIT(1);
        } else {
            CP_WAIT(0);
        }
        __syncthreads();

        const uint32_t Ab = sbase + FA_(s), Bb = sbase + FB_(s);

#pragma unroll
        for (int ks = 0; ks < 4; ks++) {
            uint32_t a[4][4];
#pragma unroll
            for (int mt = 0; mt < 4; mt++) {
                uint32_t row = (uint32_t)(wm * 64 + mt * 16 + (lane & 15));
                uint32_t aoff = SWZ((row << 7) + (ks * 16 + a_kb) * 2);
                ldsm_x4(a[mt][0], a[mt][1], a[mt][2], a[mt][3], Ab + aoff);
            }
            uint32_t b[8];
#pragma unroll
            for (int np = 0; np < 2; np++) {
                uint32_t row = (uint32_t)(wn * 32) + (np * 2 + b_nt) * 8 + b_r;
                uint32_t boff = SWZ((row << 7) + (ks * 16 + b_kb) * 2);
                ldsm_x4(b[np*4+0], b[np*4+1], b[np*4+2], b[np*4+3], Bb + boff);
            }
#pragma unroll
            for (int mt = 0; mt < 4; mt++)
#pragma unroll
                for (int nt = 0; nt < 4; nt++)
                    mma_f16(acc[mt][nt], a[mt][0], a[mt][1], a[mt][2], a[mt][3],
                            b[nt*2], b[nt*2+1]);
        }
        __syncthreads();
    }

    const int g  = lane >> 2;
    const int tg = lane & 3;
#pragma unroll
    for (int mt = 0; mt < 4; mt++) {
        int r0 = m0 + wm * 64 + mt * 16 + g;
#pragma unroll
        for (int nt = 0; nt < 4; nt++) {
            int nl = wn * 32 + nt * 8 + tg * 2;
            int n  = n0 + nl;
            float bia0 = s_bias[nl], bia1 = s_bias[nl + 1];
            float2 v0 = make_float2(acc[mt][nt][0] + bia0, acc[mt][nt][1] + bia1);
            float2 v1 = make_float2(acc[mt][nt][2] + bia0, acc[mt][nt][3] + bia1);
            size_t z0 = ((size_t)(r0 >> 6) * 128 + (n >> 5)) * 2048 + (r0 & 63) * 32 + (n & 31);
            int r1 = r0 + 8;
            size_t z1 = ((size_t)(r1 >> 6) * 128 + (n >> 5)) * 2048 + (r1 & 63) * 32 + (n & 31);
            *(float2*)&Z[z0] = v0;
            *(float2*)&Z[z1] = v1;
        }
    }
}

// ---------------------------------------------------------------------------
// Phase 2: persistent recurrence — R7 control flow, ALL single fp16.
// z_h = h_f16 @ W_f16^T (1 product, 2 ldsm/ks -> 512 KB/step SMEM traffic).
// SMEM: W 64K @0 | A 2 stages x 16K @65536 | ZX 8K @98304. Zs overlays A st0.
// ---------------------------------------------------------------------------
#define W_       0
#define AST_(s)  (65536 + (s) * 16384)
#define ZX_OFF_  98304
#define ZS_OFF_  65536
#define SMEM_DYN_ 106496

__global__ __launch_bounds__(256) void lstm_persist(
    const float* __restrict__ Zx_all,
    const __half* __restrict__ Whf,
    char* __restrict__ Hf,             // g_hf base
    const float* __restrict__ gbf, const float* __restrict__ gbi,
    const float* __restrict__ gbu, const float* __restrict__ gbo,
    float* __restrict__ out,           // [T][B][H]
    float* __restrict__ hc_tail)       // null or [hx|cx]
{
    extern __shared__ __align__(1024) char sm[];
    __shared__ float s_gb[32];
    __shared__ __align__(8) uint64_t s_mbar[3];   // stage0, stage1, zx

    const uint32_t sbase = smem_u32(sm);
    const int tid  = threadIdx.x;
    const int wid  = tid >> 5;
    const int lane = tid & 31;
    const int bx   = blockIdx.x;
    const int j0   = bx * 8;

    if (tid < 32) {
        int gate = tid >> 3, jl = tid & 7;
        const float* gp = (gate == 0) ? gbf : (gate == 1) ? gbi : (gate == 2) ? gbu : gbo;
        s_gb[tid] = gp[j0 + jl];
    }
    if (tid == 0) {
        MBARRIER_INIT(smem_u32(&s_mbar[0]), 1);
        MBARRIER_INIT(smem_u32(&s_mbar[1]), 1);
        MBARRIER_INIT(smem_u32(&s_mbar[2]), 1);
    }

    // ---- resident weights once (single fp16, 64 KB) ----
    {
        const char* w8 = (const char*)(Whf + (size_t)bx * 32 * H_);
        for (int i = tid; i < 4096; i += 256) {
            int c  = i >> 8;
            int r  = (i >> 3) & 31;
            int cg = i & 7;
            size_t goff = (size_t)r * 2048 + (size_t)c * 128 + cg * 16;
            uint32_t soff = (uint32_t)c * 4096 + SWZ((uint32_t)(r * 128 + cg * 16));
            cp_async16(sbase + W_ + soff, w8 + goff);
        }
        CP_COMMIT(); CP_WAIT(0);
        __syncthreads();
    }

    const int wm = wid & 3;
    const int wn = wid >> 2;
    const int m0 = wm * 16;

    const uint32_t a_r  = (uint32_t)(m0 + (lane & 15));
    const uint32_t a_kb = (uint32_t)((lane >> 4) << 3);
    const uint32_t b_nt = (uint32_t)((lane >> 3) >> 1);
    const uint32_t b_kb = (uint32_t)(((lane >> 3) & 1) * 8);
    const uint32_t b_r  = (uint32_t)(lane & 7);
    const uint32_t b_row = (uint32_t)(wn * 16) + b_nt * 8 + b_r;

    const uint32_t mb0 = smem_u32(&s_mbar[0]);
    const uint32_t mb1 = smem_u32(&s_mbar[1]);
    const uint32_t mbz = smem_u32(&s_mbar[2]);

    int ph[2] = {0, 0};
    int phz = 0;

    float c_reg[2] = {0.f, 0.f};

    const int hc64 = j0 >> 6;          // this CTA's produced h chunk
    const int kcb  = j0 & 63;

    for (int t = 0; t < T_; t++) {
        const char* hin = Hf + (size_t)(t & 1) * HBUF_STRIDE_;
        char* hout = Hf + (size_t)((t + 1) & 1) * HBUF_STRIDE_;

        // issue step's ZX slab + first two 128-col chunks (tid 0)
        if (tid == 0) {
            asm volatile("fence.proxy.async;" ::: "memory");
            MBARRIER_EXPECT_TX(mbz, 8192);
            cp_bulk(sbase + ZX_OFF_,
                    Zx_all + ((size_t)t * 128 + bx) * 2048, 8192, mbz);
#pragma unroll
            for (int pc = 0; pc < 2; pc++) {   // chunks 0,1 -> stages 0,1
                uint32_t mb = pc ? mb1 : mb0;
                MBARRIER_EXPECT_TX(mb, 16384);
#pragma unroll
                for (int sub = 0; sub < 2; sub++) {
                    int c64 = pc * 2 + sub;
                    cp_bulk(sbase + AST_(pc) + sub * 8192,
                            hin + (size_t)c64 * 8192, 8192, mb);
                }
            }
        }

        float acc[2][4];
#pragma unroll
        for (int nt = 0; nt < 2; nt++)
#pragma unroll
            for (int i = 0; i < 4; i++) acc[nt][i] = 0.0f;

        for (int ch = 0; ch < 8; ch++) {
            const int s = ch & 1;
            MBARRIER_WAIT_PARITY(s ? mb1 : mb0, ph[s]);
            ph[s] ^= 1;

#pragma unroll
            for (int sub = 0; sub < 2; sub++) {
                const int c64 = ch * 2 + sub;
                const uint32_t Aa = sbase + AST_(s) + sub * 8192;
                const uint32_t Bb = sbase + W_ + (uint32_t)c64 * 4096;

#pragma unroll
                for (int ks = 0; ks < 4; ks++) {
                    uint32_t aoff = SWZ((a_r << 7) + (ks * 16 + a_kb) * 2);
                    uint32_t a0, a1, a2, a3;
                    ldsm_x4(a0, a1, a2, a3, Aa + aoff);

                    uint32_t boff = SWZ((b_row << 7) + (ks * 16 + b_kb) * 2);
                    uint32_t b0, b1, b2, b3;
                    ldsm_x4(b0, b1, b2, b3, Bb + boff);

                    mma_f16(acc[0], a0, a1, a2, a3, b0, b1);
                    mma_f16(acc[1], a0, a1, a2, a3, b2, b3);
                }
            }
            __syncthreads();

            if (ch + 2 < 8 && tid == 0) {
                asm volatile("fence.proxy.async;" ::: "memory");
                uint32_t mb = s ? mb1 : mb0;
                MBARRIER_EXPECT_TX(mb, 16384);
#pragma unroll
                for (int sub = 0; sub < 2; sub++) {
                    int c64 = (ch + 2) * 2 + sub;
                    cp_bulk(sbase + AST_(s) + sub * 8192,
                            hin + (size_t)c64 * 8192, 8192, mb);
                }
            }
        }

        // stage accumulators to SMEM (overlay A stage 0)
        float* Zs = (float*)(sm + ZS_OFF_);
        {
            const int g  = lane >> 2;
            const int tg = lane & 3;
#pragma unroll
            for (int nt = 0; nt < 2; nt++) {
                int n = wn * 16 + nt * 8 + tg * 2;
                Zs[(m0 + g)     * 32 + n]     = acc[nt][0];
                Zs[(m0 + g)     * 32 + n + 1] = acc[nt][1];
                Zs[(m0 + g + 8) * 32 + n]     = acc[nt][2];
                Zs[(m0 + g + 8) * 32 + n + 1] = acc[nt][3];
            }
        }
        __syncthreads();
        MBARRIER_WAIT_PARITY(mbz, phz);
        phz ^= 1;

        // fused LSTM epilogue: 512 (b, jl) pairs, 2 per thread, c in registers
        const float* zxs = (const float*)(sm + ZX_OFF_);
        float* out_t = out + (size_t)t * BH_;
        char* hout_c = hout + (size_t)hc64 * 8192;
#pragma unroll
        for (int p0 = 0; p0 < 2; p0++) {
            int p  = tid + p0 * 256;
            int b  = p >> 3;
            int jl = p & 7;
            float4 zh  = *(const float4*)&Zs[b * 32 + jl * 4];
            float4 zx4 = *(const float4*)&zxs[b * 32 + jl * 4];

            float f  = sigf(__cosf(zh.x + zx4.x) + s_gb[0 * 8 + jl]);
            float ii = sigf(__cosf(zh.y + zx4.y) + s_gb[1 * 8 + jl]);
            float g  = tanh_fast(__cosf(zh.z + zx4.z) + s_gb[2 * 8 + jl]);
            float o  = sigf(__cosf(zh.w + zx4.w) + s_gb[3 * 8 + jl]);

            float c = f * c_reg[p0] + ii * g;
            c_reg[p0] = c;
            float h = o * tanh_fast(c);

            size_t idx = (size_t)b * H_ + j0 + jl;
            out_t[idx] = h;

            uint32_t hoff = SWZ((uint32_t)(b * 128 + (kcb + jl) * 2));
            *(__half*)(hout_c + hoff) = __float2half(h);

            if (hc_tail && t == T_ - 1) {
                hc_tail[idx] = h;
                hc_tail[(size_t)BH_ + idx] = c;
            }
        }

        // grid barrier (skip after last step)
        if (t + 1 < T_) {
            __syncthreads();
            if (tid == 0) {
                asm volatile("red.release.gpu.add.u32 [%0], 1;" :: "l"(&g_bar) : "memory");
                unsigned target = (unsigned)(t + 1) * 128u;
                unsigned v;
                do {
                    asm volatile("ld.acquire.gpu.u32 %0, [%1];" : "=r"(v) : "l"(&g_bar) : "memory");
                } while (v < target);
            }
            __syncthreads();
        }
    }
}

// ---------------------------------------------------------------------------
extern "C" void kernel_launch(void* const* d_in, const int* in_sizes, int n_in,
                              void* d_out, int out_size)
{
    const float* X   = (const float*)d_in[0];
    const float* Wf  = (const float*)d_in[1];
    const float* bf  = (const float*)d_in[2];
    const float* gbf = (const float*)d_in[3];
    const float* Wi  = (const float*)d_in[4];
    const float* bi  = (const float*)d_in[5];
    const float* gbi = (const float*)d_in[6];
    const float* Wu  = (const float*)d_in[7];
    const float* bu  = (const float*)d_in[8];
    const float* gbu = (const float*)d_in[9];
    const float* Wo  = (const float*)d_in[10];
    const float* bo  = (const float*)d_in[11];
    const float* gbo = (const float*)d_in[12];

    float* out = (float*)d_out;

    float *p_zx;
    __half *p_whf, *p_wxf, *p_xf;
    char* p_hf;
    unsigned* p_bar;
    cudaGetSymbolAddress((void**)&p_zx,  g_zx);
    cudaGetSymbolAddress((void**)&p_whf, g_whf);
    cudaGetSymbolAddress((void**)&p_wxf, g_wxf);
    cudaGetSymbolAddress((void**)&p_xf,  g_xf);
    cudaGetSymbolAddress((void**)&p_hf,  g_hf);
    cudaGetSymbolAddress((void**)&p_bar, g_bar);

    cudaFuncSetAttribute(lstm_persist, cudaFuncAttributeMaxDynamicSharedMemorySize, SMEM_DYN_);
    cudaFuncSetAttribute(gemm_tc, cudaFuncAttributeMaxDynamicSharedMemorySize, GSMEM_);

    // reset initial h buffer (parity 0) and the barrier counter
    cudaMemsetAsync(p_hf, 0, HBUF_STRIDE_);
    cudaMemsetAsync(p_bar, 0, sizeof(unsigned));

    // Phase 0: weight/input conversion (all single fp16)
    conv_w<<<(NG_ * H_) / 256, 256>>>(Wf, Wi, Wu, Wo, p_whf);
    conv_wx<<<(NG_ * D_) / 256, 256>>>(Wf, Wi, Wu, Wo, p_wxf);
    conv_x<<<(M_ * D_) / 256, 256>>>(X, p_xf);

    // Phase 1: all-timestep input projection (+bias), single fp16 GEMM
    dim3 g1(NG_ / 128, M_ / 128);
    gemm_tc<<<g1, 256, GSMEM_>>>(p_xf, p_wxf, bf, bi, bu, bo, p_zx);

    // Phase 2: persistent fused recurrence (all 256 steps in one kernel)
    const size_t TBH = (size_t)T_ * B_ * H_;
    const bool tails = out_size >= (int)(TBH + 2 * (size_t)BH_);
    lstm_persist<<<128, 256, SMEM_DYN_>>>(
        p_zx, p_whf, p_hf,
        gbf, gbi, gbu, gbo,
        out, tails ? out + TBH : nullptr);
}

// round 14
// speedup vs baseline: 2.1952x; 1.2084x over previous
#include <cuda_runtime.h>
#include <cuda_bf16.h>
#include <cuda_fp16.h>
#include <math.h>
#include <stdint.h>

#define T_  256
#define B_  64
#define D_  1024
#define H_  1024
#define DH_ 2048
#define NG_ 4096   /* 4 gates * H, packed n = j*4 + gate */
#define BH_ (B_ * H_)
#define M_  (T_ * B_)   /* 16384 */

// ---------------------------------------------------------------------------
// Device globals (scratch; no runtime allocation allowed)
// ---------------------------------------------------------------------------
// Zx in per-CTA slabs: [t][grp=0..127][64 b x 32 cols] fp32, slab = 8KB contiguous
__device__ float g_zx[(size_t)T_ * B_ * NG_];
__device__ __half g_whf[(size_t)NG_ * H_];             // packed Wh single fp16
__device__ __half g_wxf[(size_t)NG_ * D_];             // packed Wx single fp16
__device__ __half g_xf[(size_t)M_ * D_];               // X single fp16
// h double buffer, single fp16, pre-swizzled chunk-major: [buf][c64 0..15][8192 B]
// within chunk: byte off = SWZ(b*128 + (k%64)*2)
__device__ __align__(128) char g_hf[2][16][8192];
__device__ unsigned g_bar;                             // grid barrier counter

#define HBUF_STRIDE_ 131072   /* 16*8192 */

// ---------------------------------------------------------------------------
// PTX helpers (compute_103-portable)
// ---------------------------------------------------------------------------
__device__ __forceinline__ uint32_t smem_u32(const void* p) {
    uint32_t a;
    asm("{ .reg .u64 t; cvta.to.shared.u64 t, %1; cvt.u32.u64 %0, t; }" : "=r"(a) : "l"(p));
    return a;
}
__device__ __forceinline__ void cp_async16(uint32_t smem, const void* g) {
    asm volatile("cp.async.cg.shared.global [%0], [%1], 16;" :: "r"(smem), "l"(g) : "memory");
}
#define CP_COMMIT() asm volatile("cp.async.commit_group;" ::: "memory")
#define CP_WAIT(n)  asm volatile("cp.async.wait_group %0;" :: "n"(n) : "memory")

// 1D bulk copy global->shared with mbarrier completion (sm_90+, portable)
__device__ __forceinline__ void cp_bulk(uint32_t dst, const void* src, uint32_t bytes,
                                        uint32_t mbar) {
    asm volatile("cp.async.bulk.shared::cta.global.mbarrier::complete_tx::bytes "
                 "[%0], [%1], %2, [%3];"
                 :: "r"(dst), "l"(src), "r"(bytes), "r"(mbar) : "memory");
}
#define MBARRIER_INIT(mbar, cnt) \
    asm volatile("mbarrier.init.shared.b64 [%0], %1;" :: "r"((uint32_t)(mbar)), "r"((uint32_t)(cnt)) : "memory")
#define MBARRIER_EXPECT_TX(mbar, bytes) \
    asm volatile("mbarrier.arrive.expect_tx.shared.b64 _, [%0], %1;" \
        :: "r"((uint32_t)(mbar)), "r"((uint32_t)(bytes)) : "memory")
#define MBARRIER_WAIT_PARITY(mbar, parity) do { \
    uint32_t _m = (uint32_t)(mbar); uint32_t _p = (uint32_t)(parity); uint32_t _d; \
    asm volatile("{\n\t.reg .pred p;\n\t" \
        "mbarrier.try_wait.parity.acquire.cta.shared::cta.b64 p, [%1], %2;\n\t" \
        "selp.b32 %0, 1, 0, p;\n\t}" : "=r"(_d) : "r"(_m), "r"(_p) : "memory"); \
    if (!_d) { \
        asm volatile("{\n\t.reg .pred P1;\n\tWL_%=:\n\t" \
            "mbarrier.try_wait.parity.acquire.cta.shared::cta.b64 P1, [%0], %1, 0x989680;\n\t" \
            "@P1 bra.uni WD_%=;\n\tbra.uni WL_%=;\n\tWD_%=:\n\t}" \
            :: "r"(_m), "r"(_p) : "memory"); \
    } } while (0)

__device__ __forceinline__ void ldsm_x4(uint32_t& r0, uint32_t& r1, uint32_t& r2, uint32_t& r3,
                                        uint32_t addr) {
    asm volatile("ldmatrix.sync.aligned.m8n8.x4.shared.b16 {%0,%1,%2,%3}, [%4];"
                 : "=r"(r0), "=r"(r1), "=r"(r2), "=r"(r3) : "r"(addr));
}
__device__ __forceinline__ void mma_f16(float* c,
                                        uint32_t a0, uint32_t a1, uint32_t a2, uint32_t a3,
                                        uint32_t b0, uint32_t b1) {
    asm volatile("mma.sync.aligned.m16n8k16.row.col.f32.f16.f16.f32 "
                 "{%0,%1,%2,%3}, {%4,%5,%6,%7}, {%8,%9}, {%0,%1,%2,%3};"
                 : "+f"(c[0]), "+f"(c[1]), "+f"(c[2]), "+f"(c[3])
                 : "r"(a0), "r"(a1), "r"(a2), "r"(a3), "r"(b0), "r"(b1));
}
#define SWZ(off) ((off) ^ (((off) >> 3) & 0x70))

__device__ __forceinline__ float sigf(float x) { return 1.0f / (1.0f + __expf(-x)); }
__device__ __forceinline__ float tanh_fast(float x) {
    float a = fabsf(x);
    float e = __expf(-2.0f * a);
    float t = (1.0f - e) / (1.0f + e);
    return copysignf(t, x);
}

// ---------------------------------------------------------------------------
// Phase 0a: pack Wh (h-part) single fp16. Row n=(j<<2)|gate.
// ---------------------------------------------------------------------------
__global__ __launch_bounds__(256) void conv_w(
    const float* __restrict__ Wf, const float* __restrict__ Wi,
    const float* __restrict__ Wu, const float* __restrict__ Wo,
    __half* __restrict__ wq)
{
    size_t idx = (size_t)blockIdx.x * 256 + threadIdx.x;   // over NG_*H_
    int n = (int)(idx >> 10);
    int k = (int)(idx & 1023);
    int j = n >> 2, gate = n & 3;
    const float* W = (gate == 0) ? Wf : (gate == 1) ? Wi : (gate == 2) ? Wu : Wo;
    wq[idx] = __float2half(W[(size_t)j * DH_ + D_ + k]);
}

// Phase 0b: pack Wx (x-part) single fp16. Row n=(j<<2)|gate.
__global__ __launch_bounds__(256) void conv_wx(
    const float* __restrict__ Wf, const float* __restrict__ Wi,
    const float* __restrict__ Wu, const float* __restrict__ Wo,
    __half* __restrict__ wq)
{
    size_t idx = (size_t)blockIdx.x * 256 + threadIdx.x;   // over NG_*D_
    int n = (int)(idx >> 10);
    int k = (int)(idx & 1023);
    int j = n >> 2, gate = n & 3;
    const float* W = (gate == 0) ? Wf : (gate == 1) ? Wi : (gate == 2) ? Wu : Wo;
    wq[idx] = __float2half(W[(size_t)j * DH_ + k]);
}

// Phase 0c: X single fp16.
__global__ __launch_bounds__(256) void conv_x(
    const float* __restrict__ X, __half* __restrict__ xq)
{
    size_t idx = (size_t)blockIdx.x * 256 + threadIdx.x;   // over M_*D_
    xq[idx] = __float2half(X[idx]);
}

// ---------------------------------------------------------------------------
// Phase 1: input projection on tensor cores, single fp16 (R11-proven).
// Z(M x NG, packed) = X @ Wx^T + bias, fp32 out, per-CTA slab layout:
//   zidx(m,n) = ((m>>6)*128 + (n>>5))*2048 + (m&63)*32 + (n&31)
// ---------------------------------------------------------------------------
#define FA_(s)   ((s) * 32768)
#define FB_(s)   ((s) * 32768 + 16384)
#define GSMEM_   65536

__global__ __launch_bounds__(256) void gemm_tc(
    const __half* __restrict__ Xq,
    const __half* __restrict__ Wq,
    const float* __restrict__ bf, const float* __restrict__ bi,
    const float* __restrict__ bu, const float* __restrict__ bo,
    float* __restrict__ Z)
{
    extern __shared__ __align__(1024) char sm[];
    __shared__ float s_bias[128];

    const uint32_t sbase = smem_u32(sm);
    const int tid  = threadIdx.x;
    const int wid  = tid >> 5;
    const int lane = tid & 31;
    const int n0   = blockIdx.x * 128;   // packed col base
    const int m0   = blockIdx.y * 128;

    const int wm = wid & 1;              // M half (64 rows)
    const int wn = wid >> 1;             // N quarter (32 cols)

    if (tid < 128) {
        int n = n0 + tid, gate = n & 3, j = n >> 2;
        const float* Ba = (gate == 0) ? bf : (gate == 1) ? bi : (gate == 2) ? bu : bo;
        s_bias[tid] = Ba[j];
    }

    const char* x8 = (const char*)(Xq + (size_t)m0 * D_);
    const char* w8 = (const char*)(Wq + (size_t)n0 * D_);

    auto load_chunk = [&](int ch, int s) {
#pragma unroll
        for (int r4 = 0; r4 < 4; r4++) {
            int idx = tid + r4 * 256;          // 1024 slots = 128 rows x 8 cg
            int row = idx >> 3, cg = idx & 7;
            size_t goff = (size_t)row * 2048 + (size_t)ch * 128 + cg * 16;
            uint32_t soff = SWZ((uint32_t)(row * 128 + cg * 16));
            cp_async16(sbase + FA_(s) + soff, x8 + goff);
            cp_async16(sbase + FB_(s) + soff, w8 + goff);
        }
    };

    float acc[4][4][4];
#pragma unroll
    for (int mt = 0; mt < 4; mt++)
#pragma unroll
        for (int nt = 0; nt < 4; nt++)
#pragma unroll
            for (int i = 0; i < 4; i++) acc[mt][nt][i] = 0.0f;

    const uint32_t a_kb = (uint32_t)((lane >> 4) << 3);
    const uint32_t b_nt = (uint32_t)((lane >> 3) >> 1);
    const uint32_t b_kb = (uint32_t)(((lane >> 3) & 1) * 8);
    const uint32_t b_r  = (uint32_t)(lane & 7);

    load_chunk(0, 0);
    CP_COMMIT();

    for (int ch = 0; ch < 16; ch++) {
        const int s = ch & 1;
        if (ch + 1 < 16) {
            load_chunk(ch + 1, s ^ 1);
            CP_COMMIT();
            CP_WAIT(1);
        } else {
            CP_WAIT(0);
        }
        __syncthreads();

        const uint32_t Ab = sbase + FA_(s), Bb = sbase + FB_(s);

#pragma unroll
        for (int ks = 0; ks < 4; ks++) {
            uint32_t a[4][4];
#pragma unroll
            for (int mt = 0; mt < 4; mt++) {
                uint32_t row = (uint32_t)(wm * 64 + mt * 16 + (lane & 15));
                uint32_t aoff = SWZ((row << 7) + (ks * 16 + a_kb) * 2);
                ldsm_x4(a[mt][0], a[mt][1], a[mt][2], a[mt][3], Ab + aoff);
            }
            uint32_t b[8];
#pragma unroll
            for (int np = 0; np < 2; np++) {
                uint32_t row = (uint32_t)(wn * 32) + (np * 2 + b_nt) * 8 + b_r;
                uint32_t boff = SWZ((row << 7) + (ks * 16 + b_kb) * 2);
                ldsm_x4(b[np*4+0], b[np*4+1], b[np*4+2], b[np*4+3], Bb + boff);
            }
#pragma unroll
            for (int mt = 0; mt < 4; mt++)
#pragma unroll
                for (int nt = 0; nt < 4; nt++)
                    mma_f16(acc[mt][nt], a[mt][0], a[mt][1], a[mt][2], a[mt][3],
                            b[nt*2], b[nt*2+1]);
        }
        __syncthreads();
    }

    const int g  = lane >> 2;
    const int tg = lane & 3;
#pragma unroll
    for (int mt = 0; mt < 4; mt++) {
        int r0 = m0 + wm * 64 + mt * 16 + g;
#pragma unroll
        for (int nt = 0; nt < 4; nt++) {
            int nl = wn * 32 + nt * 8 + tg * 2;
            int n  = n0 + nl;
            float bia0 = s_bias[nl], bia1 = s_bias[nl + 1];
            float2 v0 = make_float2(acc[mt][nt][0] + bia0, acc[mt][nt][1] + bia1);
            float2 v1 = make_float2(acc[mt][nt][2] + bia0, acc[mt][nt][3] + bia1);
            size_t z0 = ((size_t)(r0 >> 6) * 128 + (n >> 5)) * 2048 + (r0 & 63) * 32 + (n & 31);
            int r1 = r0 + 8;
            size_t z1 = ((size_t)(r1 >> 6) * 128 + (n >> 5)) * 2048 + (r1 & 63) * 32 + (n & 31);
            *(float2*)&Z[z0] = v0;
            *(float2*)&Z[z1] = v1;
        }
    }
}

// ---------------------------------------------------------------------------
// Phase 2: persistent recurrence — R13 structure, 256-col chunks (4/step).
// z_h = h_f16 @ W_f16^T. 2-stage x 32 KB pipeline -> 4 waits + 4 syncthreads
// per step instead of 8.
// SMEM: W 64K @0 | A 2 stages x 32K @65536 | ZX 8K @131072. Zs overlays A st0.
// ---------------------------------------------------------------------------
#define W_       0
#define AST_(s)  (65536 + (s) * 32768)
#define ZX_OFF_  131072
#define ZS_OFF_  65536
#define SMEM_DYN_ 139264

__global__ __launch_bounds__(256) void lstm_persist(
    const float* __restrict__ Zx_all,
    const __half* __restrict__ Whf,
    char* __restrict__ Hf,             // g_hf base
    const float* __restrict__ gbf, const float* __restrict__ gbi,
    const float* __restrict__ gbu, const float* __restrict__ gbo,
    float* __restrict__ out,           // [T][B][H]
    float* __restrict__ hc_tail)       // null or [hx|cx]
{
    extern __shared__ __align__(1024) char sm[];
    __shared__ float s_gb[32];
    __shared__ __align__(8) uint64_t s_mbar[3];   // stage0, stage1, zx

    const uint32_t sbase = smem_u32(sm);
    const int tid  = threadIdx.x;
    const int wid  = tid >> 5;
    const int lane = tid & 31;
    const int bx   = blockIdx.x;
    const int j0   = bx * 8;

    if (tid < 32) {
        int gate = tid >> 3, jl = tid & 7;
        const float* gp = (gate == 0) ? gbf : (gate == 1) ? gbi : (gate == 2) ? gbu : gbo;
        s_gb[tid] = gp[j0 + jl];
    }
    if (tid == 0) {
        MBARRIER_INIT(smem_u32(&s_mbar[0]), 1);
        MBARRIER_INIT(smem_u32(&s_mbar[1]), 1);
        MBARRIER_INIT(smem_u32(&s_mbar[2]), 1);
    }

    // ---- resident weights once (single fp16, 64 KB) ----
    {
        const char* w8 = (const char*)(Whf + (size_t)bx * 32 * H_);
        for (int i = tid; i < 4096; i += 256) {
            int c  = i >> 8;
            int r  = (i >> 3) & 31;
            int cg = i & 7;
            size_t goff = (size_t)r * 2048 + (size_t)c * 128 + cg * 16;
            uint32_t soff = (uint32_t)c * 4096 + SWZ((uint32_t)(r * 128 + cg * 16));
            cp_async16(sbase + W_ + soff, w8 + goff);
        }
        CP_COMMIT(); CP_WAIT(0);
        __syncthreads();
    }

    const int wm = wid & 3;
    const int wn = wid >> 2;
    const int m0 = wm * 16;

    const uint32_t a_r  = (uint32_t)(m0 + (lane & 15));
    const uint32_t a_kb = (uint32_t)((lane >> 4) << 3);
    const uint32_t b_nt = (uint32_t)((lane >> 3) >> 1);
    const uint32_t b_kb = (uint32_t)(((lane >> 3) & 1) * 8);
    const uint32_t b_r  = (uint32_t)(lane & 7);
    const uint32_t b_row = (uint32_t)(wn * 16) + b_nt * 8 + b_r;

    const uint32_t mb0 = smem_u32(&s_mbar[0]);
    const uint32_t mb1 = smem_u32(&s_mbar[1]);
    const uint32_t mbz = smem_u32(&s_mbar[2]);

    int ph[2] = {0, 0};
    int phz = 0;

    float c_reg[2] = {0.f, 0.f};

    const int hc64 = j0 >> 6;          // this CTA's produced h chunk
    const int kcb  = j0 & 63;

    for (int t = 0; t < T_; t++) {
        const char* hin = Hf + (size_t)(t & 1) * HBUF_STRIDE_;
        char* hout = Hf + (size_t)((t + 1) & 1) * HBUF_STRIDE_;

        // issue step's ZX slab + first two 256-col chunks (tid 0)
        if (tid == 0) {
            asm volatile("fence.proxy.async;" ::: "memory");
            MBARRIER_EXPECT_TX(mbz, 8192);
            cp_bulk(sbase + ZX_OFF_,
                    Zx_all + ((size_t)t * 128 + bx) * 2048, 8192, mbz);
#pragma unroll
            for (int pc = 0; pc < 2; pc++) {   // chunks 0,1 -> stages 0,1
                uint32_t mb = pc ? mb1 : mb0;
                MBARRIER_EXPECT_TX(mb, 32768);
#pragma unroll
                for (int sub = 0; sub < 4; sub++) {
                    int c64 = pc * 4 + sub;
                    cp_bulk(sbase + AST_(pc) + sub * 8192,
                            hin + (size_t)c64 * 8192, 8192, mb);
                }
            }
        }

        float acc[2][4];
#pragma unroll
        for (int nt = 0; nt < 2; nt++)
#pragma unroll
            for (int i = 0; i < 4; i++) acc[nt][i] = 0.0f;

        for (int ch = 0; ch < 4; ch++) {
            const int s = ch & 1;
            MBARRIER_WAIT_PARITY(s ? mb1 : mb0, ph[s]);
            ph[s] ^= 1;

#pragma unroll
            for (int sub = 0; sub < 4; sub++) {
                const int c64 = ch * 4 + sub;
                const uint32_t Aa = sbase + AST_(s) + sub * 8192;
                const uint32_t Bb = sbase + W_ + (uint32_t)c64 * 4096;

#pragma unroll
                for (int ks = 0; ks < 4; ks++) {
                    uint32_t aoff = SWZ((a_r << 7) + (ks * 16 + a_kb) * 2);
                    uint32_t a0, a1, a2, a3;
                    ldsm_x4(a0, a1, a2, a3, Aa + aoff);

                    uint32_t boff = SWZ((b_row << 7) + (ks * 16 + b_kb) * 2);
                    uint32_t b0, b1, b2, b3;
                    ldsm_x4(b0, b1, b2, b3, Bb + boff);

                    mma_f16(acc[0], a0, a1, a2, a3, b0, b1);
                    mma_f16(acc[1], a0, a1, a2, a3, b2, b3);
                }
            }
            __syncthreads();

            if (ch + 2 < 4 && tid == 0) {
                asm volatile("fence.proxy.async;" ::: "memory");
                uint32_t mb = s ? mb1 : mb0;
                MBARRIER_EXPECT_TX(mb, 32768);
#pragma unroll
                for (int sub = 0; sub < 4; sub++) {
                    int c64 = (ch + 2) * 4 + sub;
                    cp_bulk(sbase + AST_(s) + sub * 8192,
                            hin + (size_t)c64 * 8192, 8192, mb);
                }
            }
        }

        // stage accumulators to SMEM (overlay A stage 0)
        float* Zs = (float*)(sm + ZS_OFF_);
        {
            const int g  = lane >> 2;
            const int tg = lane & 3;
#pragma unroll
            for (int nt = 0; nt < 2; nt++) {
                int n = wn * 16 + nt * 8 + tg * 2;
                Zs[(m0 + g)     * 32 + n]     = acc[nt][0];
                Zs[(m0 + g)     * 32 + n + 1] = acc[nt][1];
                Zs[(m0 + g + 8) * 32 + n]     = acc[nt][2];
                Zs[(m0 + g + 8) * 32 + n + 1] = acc[nt][3];
            }
        }
        __syncthreads();
        MBARRIER_WAIT_PARITY(mbz, phz);
        phz ^= 1;

        // fused LSTM epilogue: 512 (b, jl) pairs, 2 per thread, c in registers
        const float* zxs = (const float*)(sm + ZX_OFF_);
        float* out_t = out + (size_t)t * BH_;
        char* hout_c = hout + (size_t)hc64 * 8192;
#pragma unroll
        for (int p0 = 0; p0 < 2; p0++) {
            int p  = tid + p0 * 256;
            int b  = p >> 3;
            int jl = p & 7;
            float4 zh  = *(const float4*)&Zs[b * 32 + jl * 4];
            float4 zx4 = *(const float4*)&zxs[b * 32 + jl * 4];

            float f  = sigf(__cosf(zh.x + zx4.x) + s_gb[0 * 8 + jl]);
            float ii = sigf(__cosf(zh.y + zx4.y) + s_gb[1 * 8 + jl]);
            float g  = tanh_fast(__cosf(zh.z + zx4.z) + s_gb[2 * 8 + jl]);
            float o  = sigf(__cosf(zh.w + zx4.w) + s_gb[3 * 8 + jl]);

            float c = f * c_reg[p0] + ii * g;
            c_reg[p0] = c;
            float h = o * tanh_fast(c);

            size_t idx = (size_t)b * H_ + j0 + jl;
            out_t[idx] = h;

            uint32_t hoff = SWZ((uint32_t)(b * 128 + (kcb + jl) * 2));
            *(__half*)(hout_c + hoff) = __float2half(h);

            if (hc_tail && t == T_ - 1) {
                hc_tail[idx] = h;
                hc_tail[(size_t)BH_ + idx] = c;
            }
        }

        // grid barrier (skip after last step)
        if (t + 1 < T_) {
            __syncthreads();
            if (tid == 0) {
                asm volatile("red.release.gpu.add.u32 [%0], 1;" :: "l"(&g_bar) : "memory");
                unsigned target = (unsigned)(t + 1) * 128u;
                unsigned v;
                do {
                    asm volatile("ld.acquire.gpu.u32 %0, [%1];" : "=r"(v) : "l"(&g_bar) : "memory");
                } while (v < target);
            }
            __syncthreads();
        }
    }
}

// ---------------------------------------------------------------------------
extern "C" void kernel_launch(void* const* d_in, const int* in_sizes, int n_in,
                              void* d_out, int out_size)
{
    const float* X   = (const float*)d_in[0];
    const float* Wf  = (const float*)d_in[1];
    const float* bf  = (const float*)d_in[2];
    const float* gbf = (const float*)d_in[3];
    const float* Wi  = (const float*)d_in[4];
    const float* bi  = (const float*)d_in[5];
    const float* gbi = (const float*)d_in[6];
    const float* Wu  = (const float*)d_in[7];
    const float* bu  = (const float*)d_in[8];
    const float* gbu = (const float*)d_in[9];
    const float* Wo  = (const float*)d_in[10];
    const float* bo  = (const float*)d_in[11];
    const float* gbo = (const float*)d_in[12];

    float* out = (float*)d_out;

    float *p_zx;
    __half *p_whf, *p_wxf, *p_xf;
    char* p_hf;
    unsigned* p_bar;
    cudaGetSymbolAddress((void**)&p_zx,  g_zx);
    cudaGetSymbolAddress((void**)&p_whf, g_whf);
    cudaGetSymbolAddress((void**)&p_wxf, g_wxf);
    cudaGetSymbolAddress((void**)&p_xf,  g_xf);
    cudaGetSymbolAddress((void**)&p_hf,  g_hf);
    cudaGetSymbolAddress((void**)&p_bar, g_bar);

    cudaFuncSetAttribute(lstm_persist, cudaFuncAttributeMaxDynamicSharedMemorySize, SMEM_DYN_);
    cudaFuncSetAttribute(gemm_tc, cudaFuncAttributeMaxDynamicSharedMemorySize, GSMEM_);

    // reset initial h buffer (parity 0) and the barrier counter
    cudaMemsetAsync(p_hf, 0, HBUF_STRIDE_);
    cudaMemsetAsync(p_bar, 0, sizeof(unsigned));

    // Phase 0: weight/input conversion (all single fp16)
    conv_w<<<(NG_ * H_) / 256, 256>>>(Wf, Wi, Wu, Wo, p_whf);
    conv_wx<<<(NG_ * D_) / 256, 256>>>(Wf, Wi, Wu, Wo, p_wxf);
    conv_x<<<(M_ * D_) / 256, 256>>>(X, p_xf);

    // Phase 1: all-timestep input projection (+bias), single fp16 GEMM
    dim3 g1(NG_ / 128, M_ / 128);
    gemm_tc<<<g1, 256, GSMEM_>>>(p_xf, p_wxf, bf, bi, bu, bo, p_zx);

    // Phase 2: persistent fused recurrence (all 256 steps in one kernel)
    const size_t TBH = (size_t)T_ * B_ * H_;
    const bool tails = out_size >= (int)(TBH + 2 * (size_t)BH_);
    lstm_persist<<<128, 256, SMEM_DYN_>>>(
        p_zx, p_whf, p_hf,
        gbf, gbi, gbu, gbo,
        out, tails ? out + TBH : nullptr);
}

// round 15
// speedup vs baseline: 2.4258x; 1.1051x over previous
#include <cuda_runtime.h>
#include <cuda_bf16.h>
#include <cuda_fp16.h>
#include <math.h>
#include <stdint.h>

#define T_  256
#define B_  64
#define D_  1024
#define H_  1024
#define DH_ 2048
#define NG_ 4096   /* 4 gates * H, packed n = j*4 + gate */
#define BH_ (B_ * H_)
#define M_  (T_ * B_)   /* 16384 */

// ---------------------------------------------------------------------------
// Device globals (scratch; no runtime allocation allowed)
// ---------------------------------------------------------------------------
// Zx in per-CTA slabs: [t][grp=0..127][64 b x 32 cols] fp32, slab = 8KB contiguous
__device__ float g_zx[(size_t)T_ * B_ * NG_];
__device__ __half g_whf[(size_t)NG_ * H_];             // packed Wh single fp16
__device__ __half g_wxf[(size_t)NG_ * D_];             // packed Wx single fp16
__device__ __half g_xf[(size_t)M_ * D_];               // X single fp16
// h double buffer, single fp16, pre-swizzled chunk-major: [buf][c64 0..15][8192 B]
// within chunk: byte off = SWZ(b*128 + (k%64)*2)
__device__ __align__(128) char g_hf[2][16][8192];
__device__ unsigned g_bar;                             // grid barrier counter

#define HBUF_STRIDE_ 131072   /* 16*8192 */

// ---------------------------------------------------------------------------
// PTX helpers (compute_103-portable)
// ---------------------------------------------------------------------------
__device__ __forceinline__ uint32_t smem_u32(const void* p) {
    uint32_t a;
    asm("{ .reg .u64 t; cvta.to.shared.u64 t, %1; cvt.u32.u64 %0, t; }" : "=r"(a) : "l"(p));
    return a;
}
__device__ __forceinline__ void cp_async16(uint32_t smem, const void* g) {
    asm volatile("cp.async.cg.shared.global [%0], [%1], 16;" :: "r"(smem), "l"(g) : "memory");
}
#define CP_COMMIT() asm volatile("cp.async.commit_group;" ::: "memory")
#define CP_WAIT(n)  asm volatile("cp.async.wait_group %0;" :: "n"(n) : "memory")

// 1D bulk copy global->shared with mbarrier completion (sm_90+, portable)
__device__ __forceinline__ void cp_bulk(uint32_t dst, const void* src, uint32_t bytes,
                                        uint32_t mbar) {
    asm volatile("cp.async.bulk.shared::cta.global.mbarrier::complete_tx::bytes "
                 "[%0], [%1], %2, [%3];"
                 :: "r"(dst), "l"(src), "r"(bytes), "r"(mbar) : "memory");
}
#define MBARRIER_INIT(mbar, cnt) \
    asm volatile("mbarrier.init.shared.b64 [%0], %1;" :: "r"((uint32_t)(mbar)), "r"((uint32_t)(cnt)) : "memory")
#define MBARRIER_EXPECT_TX(mbar, bytes) \
    asm volatile("mbarrier.arrive.expect_tx.shared.b64 _, [%0], %1;" \
        :: "r"((uint32_t)(mbar)), "r"((uint32_t)(bytes)) : "memory")
#define MBARRIER_WAIT_PARITY(mbar, parity) do { \
    uint32_t _m = (uint32_t)(mbar); uint32_t _p = (uint32_t)(parity); uint32_t _d; \
    asm volatile("{\n\t.reg .pred p;\n\t" \
        "mbarrier.try_wait.parity.acquire.cta.shared::cta.b64 p, [%1], %2;\n\t" \
        "selp.b32 %0, 1, 0, p;\n\t}" : "=r"(_d) : "r"(_m), "r"(_p) : "memory"); \
    if (!_d) { \
        asm volatile("{\n\t.reg .pred P1;\n\tWL_%=:\n\t" \
            "mbarrier.try_wait.parity.acquire.cta.shared::cta.b64 P1, [%0], %1, 0x989680;\n\t" \
            "@P1 bra.uni WD_%=;\n\tbra.uni WL_%=;\n\tWD_%=:\n\t}" \
            :: "r"(_m), "r"(_p) : "memory"); \
    } } while (0)

__device__ __forceinline__ void ldsm_x4(uint32_t& r0, uint32_t& r1, uint32_t& r2, uint32_t& r3,
                                        uint32_t addr) {
    asm volatile("ldmatrix.sync.aligned.m8n8.x4.shared.b16 {%0,%1,%2,%3}, [%4];"
                 : "=r"(r0), "=r"(r1), "=r"(r2), "=r"(r3) : "r"(addr));
}
__device__ __forceinline__ void mma_f16(float* c,
                                        uint32_t a0, uint32_t a1, uint32_t a2, uint32_t a3,
                                        uint32_t b0, uint32_t b1) {
    asm volatile("mma.sync.aligned.m16n8k16.row.col.f32.f16.f16.f32 "
                 "{%0,%1,%2,%3}, {%4,%5,%6,%7}, {%8,%9}, {%0,%1,%2,%3};"
                 : "+f"(c[0]), "+f"(c[1]), "+f"(c[2]), "+f"(c[3])
                 : "r"(a0), "r"(a1), "r"(a2), "r"(a3), "r"(b0), "r"(b1));
}
#define SWZ(off) ((off) ^ (((off) >> 3) & 0x70))

__device__ __forceinline__ float sigf(float x) { return 1.0f / (1.0f + __expf(-x)); }
__device__ __forceinline__ float tanh_fast(float x) {
    float a = fabsf(x);
    float e = __expf(-2.0f * a);
    float t = (1.0f - e) / (1.0f + e);
    return copysignf(t, x);
}

// ---------------------------------------------------------------------------
// Phase 0a: pack Wh (h-part) single fp16. Row n=(j<<2)|gate.
// ---------------------------------------------------------------------------
__global__ __launch_bounds__(256) void conv_w(
    const float* __restrict__ Wf, const float* __restrict__ Wi,
    const float* __restrict__ Wu, const float* __restrict__ Wo,
    __half* __restrict__ wq)
{
    size_t idx = (size_t)blockIdx.x * 256 + threadIdx.x;   // over NG_*H_
    int n = (int)(idx >> 10);
    int k = (int)(idx & 1023);
    int j = n >> 2, gate = n & 3;
    const float* W = (gate == 0) ? Wf : (gate == 1) ? Wi : (gate == 2) ? Wu : Wo;
    wq[idx] = __float2half(W[(size_t)j * DH_ + D_ + k]);
}

// Phase 0b: pack Wx (x-part) single fp16. Row n=(j<<2)|gate.
__global__ __launch_bounds__(256) void conv_wx(
    const float* __restrict__ Wf, const float* __restrict__ Wi,
    const float* __restrict__ Wu, const float* __restrict__ Wo,
    __half* __restrict__ wq)
{
    size_t idx = (size_t)blockIdx.x * 256 + threadIdx.x;   // over NG_*D_
    int n = (int)(idx >> 10);
    int k = (int)(idx & 1023);
    int j = n >> 2, gate = n & 3;
    const float* W = (gate == 0) ? Wf : (gate == 1) ? Wi : (gate == 2) ? Wu : Wo;
    wq[idx] = __float2half(W[(size_t)j * DH_ + k]);
}

// Phase 0c: X single fp16.
__global__ __launch_bounds__(256) void conv_x(
    const float* __restrict__ X, __half* __restrict__ xq)
{
    size_t idx = (size_t)blockIdx.x * 256 + threadIdx.x;   // over M_*D_
    xq[idx] = __float2half(X[idx]);
}

// ---------------------------------------------------------------------------
// Phase 1: input projection on tensor cores, single fp16 (R11-proven).
// Z(M x NG, packed) = X @ Wx^T + bias, fp32 out, per-CTA slab layout:
//   zidx(m,n) = ((m>>6)*128 + (n>>5))*2048 + (m&63)*32 + (n&31)
// ---------------------------------------------------------------------------
#define FA_(s)   ((s) * 32768)
#define FB_(s)   ((s) * 32768 + 16384)
#define GSMEM_   65536

__global__ __launch_bounds__(256) void gemm_tc(
    const __half* __restrict__ Xq,
    const __half* __restrict__ Wq,
    const float* __restrict__ bf, const float* __restrict__ bi,
    const float* __restrict__ bu, const float* __restrict__ bo,
    float* __restrict__ Z)
{
    extern __shared__ __align__(1024) char sm[];
    __shared__ float s_bias[128];

    const uint32_t sbase = smem_u32(sm);
    const int tid  = threadIdx.x;
    const int wid  = tid >> 5;
    const int lane = tid & 31;
    const int n0   = blockIdx.x * 128;   // packed col base
    const int m0   = blockIdx.y * 128;

    const int wm = wid & 1;              // M half (64 rows)
    const int wn = wid >> 1;             // N quarter (32 cols)

    if (tid < 128) {
        int n = n0 + tid, gate = n & 3, j = n >> 2;
        const float* Ba = (gate == 0) ? bf : (gate == 1) ? bi : (gate == 2) ? bu : bo;
        s_bias[tid] = Ba[j];
    }

    const char* x8 = (const char*)(Xq + (size_t)m0 * D_);
    const char* w8 = (const char*)(Wq + (size_t)n0 * D_);

    auto load_chunk = [&](int ch, int s) {
#pragma unroll
        for (int r4 = 0; r4 < 4; r4++) {
            int idx = tid + r4 * 256;          // 1024 slots = 128 rows x 8 cg
            int row = idx >> 3, cg = idx & 7;
            size_t goff = (size_t)row * 2048 + (size_t)ch * 128 + cg * 16;
            uint32_t soff = SWZ((uint32_t)(row * 128 + cg * 16));
            cp_async16(sbase + FA_(s) + soff, x8 + goff);
            cp_async16(sbase + FB_(s) + soff, w8 + goff);
        }
    };

    float acc[4][4][4];
#pragma unroll
    for (int mt = 0; mt < 4; mt++)
#pragma unroll
        for (int nt = 0; nt < 4; nt++)
#pragma unroll
            for (int i = 0; i < 4; i++) acc[mt][nt][i] = 0.0f;

    const uint32_t a_kb = (uint32_t)((lane >> 4) << 3);
    const uint32_t b_nt = (uint32_t)((lane >> 3) >> 1);
    const uint32_t b_kb = (uint32_t)(((lane >> 3) & 1) * 8);
    const uint32_t b_r  = (uint32_t)(lane & 7);

    load_chunk(0, 0);
    CP_COMMIT();

    for (int ch = 0; ch < 16; ch++) {
        const int s = ch & 1;
        if (ch + 1 < 16) {
            load_chunk(ch + 1, s ^ 1);
            CP_COMMIT();
            CP_WAIT(1);
        } else {
            CP_WAIT(0);
        }
        __syncthreads();

        const uint32_t Ab = sbase + FA_(s), Bb = sbase + FB_(s);

#pragma unroll
        for (int ks = 0; ks < 4; ks++) {
            uint32_t a[4][4];
#pragma unroll
            for (int mt = 0; mt < 4; mt++) {
                uint32_t row = (uint32_t)(wm * 64 + mt * 16 + (lane & 15));
                uint32_t aoff = SWZ((row << 7) + (ks * 16 + a_kb) * 2);
                ldsm_x4(a[mt][0], a[mt][1], a[mt][2], a[mt][3], Ab + aoff);
            }
            uint32_t b[8];
#pragma unroll
            for (int np = 0; np < 2; np++) {
                uint32_t row = (uint32_t)(wn * 32) + (np * 2 + b_nt) * 8 + b_r;
                uint32_t boff = SWZ((row << 7) + (ks * 16 + b_kb) * 2);
                ldsm_x4(b[np*4+0], b[np*4+1], b[np*4+2], b[np*4+3], Bb + boff);
            }
#pragma unroll
            for (int mt = 0; mt < 4; mt++)
#pragma unroll
                for (int nt = 0; nt < 4; nt++)
                    mma_f16(acc[mt][nt], a[mt][0], a[mt][1], a[mt][2], a[mt][3],
                            b[nt*2], b[nt*2+1]);
        }
        __syncthreads();
    }

    const int g  = lane >> 2;
    const int tg = lane & 3;
#pragma unroll
    for (int mt = 0; mt < 4; mt++) {
        int r0 = m0 + wm * 64 + mt * 16 + g;
#pragma unroll
        for (int nt = 0; nt < 4; nt++) {
            int nl = wn * 32 + nt * 8 + tg * 2;
            int n  = n0 + nl;
            float bia0 = s_bias[nl], bia1 = s_bias[nl + 1];
            float2 v0 = make_float2(acc[mt][nt][0] + bia0, acc[mt][nt][1] + bia1);
            float2 v1 = make_float2(acc[mt][nt][2] + bia0, acc[mt][nt][3] + bia1);
            size_t z0 = ((size_t)(r0 >> 6) * 128 + (n >> 5)) * 2048 + (r0 & 63) * 32 + (n & 31);
            int r1 = r0 + 8;
            size_t z1 = ((size_t)(r1 >> 6) * 128 + (n >> 5)) * 2048 + (r1 & 63) * 32 + (n & 31);
            *(float2*)&Z[z0] = v0;
            *(float2*)&Z[z1] = v1;
        }
    }
}

// ---------------------------------------------------------------------------
// Phase 2: persistent recurrence — 512-col chunks (2/step), all copies issued
// in the prologue, NO refills, ONE syncthreads after the MMA loop.
// z_h = h_f16 @ W_f16^T.
// SMEM: W 64K @0 | A 2 stages x 64K @65536 | ZX 8K @196608. Zs overlays A st0.
// ---------------------------------------------------------------------------
#define W_       0
#define AST_(s)  (65536 + (s) * 65536)
#define ZX_OFF_  196608
#define ZS_OFF_  65536
#define SMEM_DYN_ 204800

__global__ __launch_bounds__(256) void lstm_persist(
    const float* __restrict__ Zx_all,
    const __half* __restrict__ Whf,
    char* __restrict__ Hf,             // g_hf base
    const float* __restrict__ gbf, const float* __restrict__ gbi,
    const float* __restrict__ gbu, const float* __restrict__ gbo,
    float* __restrict__ out,           // [T][B][H]
    float* __restrict__ hc_tail)       // null or [hx|cx]
{
    extern __shared__ __align__(1024) char sm[];
    __shared__ float s_gb[32];
    __shared__ __align__(8) uint64_t s_mbar[3];   // stage0, stage1, zx

    const uint32_t sbase = smem_u32(sm);
    const int tid  = threadIdx.x;
    const int wid  = tid >> 5;
    const int lane = tid & 31;
    const int bx   = blockIdx.x;
    const int j0   = bx * 8;

    if (tid < 32) {
        int gate = tid >> 3, jl = tid & 7;
        const float* gp = (gate == 0) ? gbf : (gate == 1) ? gbi : (gate == 2) ? gbu : gbo;
        s_gb[tid] = gp[j0 + jl];
    }
    if (tid == 0) {
        MBARRIER_INIT(smem_u32(&s_mbar[0]), 1);
        MBARRIER_INIT(smem_u32(&s_mbar[1]), 1);
        MBARRIER_INIT(smem_u32(&s_mbar[2]), 1);
    }

    // ---- resident weights once (single fp16, 64 KB) ----
    {
        const char* w8 = (const char*)(Whf + (size_t)bx * 32 * H_);
        for (int i = tid; i < 4096; i += 256) {
            int c  = i >> 8;
            int r  = (i >> 3) & 31;
            int cg = i & 7;
            size_t goff = (size_t)r * 2048 + (size_t)c * 128 + cg * 16;
            uint32_t soff = (uint32_t)c * 4096 + SWZ((uint32_t)(r * 128 + cg * 16));
            cp_async16(sbase + W_ + soff, w8 + goff);
        }
        CP_COMMIT(); CP_WAIT(0);
        __syncthreads();
    }

    const int wm = wid & 3;
    const int wn = wid >> 2;
    const int m0 = wm * 16;

    const uint32_t a_r  = (uint32_t)(m0 + (lane & 15));
    const uint32_t a_kb = (uint32_t)((lane >> 4) << 3);
    const uint32_t b_nt = (uint32_t)((lane >> 3) >> 1);
    const uint32_t b_kb = (uint32_t)(((lane >> 3) & 1) * 8);
    const uint32_t b_r  = (uint32_t)(lane & 7);
    const uint32_t b_row = (uint32_t)(wn * 16) + b_nt * 8 + b_r;

    const uint32_t mb0 = smem_u32(&s_mbar[0]);
    const uint32_t mb1 = smem_u32(&s_mbar[1]);
    const uint32_t mbz = smem_u32(&s_mbar[2]);

    int ph[2] = {0, 0};
    int phz = 0;

    float c_reg[2] = {0.f, 0.f};

    const int hc64 = j0 >> 6;          // this CTA's produced h chunk
    const int kcb  = j0 & 63;

    for (int t = 0; t < T_; t++) {
        const char* hin = Hf + (size_t)(t & 1) * HBUF_STRIDE_;
        char* hout = Hf + (size_t)((t + 1) & 1) * HBUF_STRIDE_;

        // prologue: ZX slab + BOTH 512-col chunks (tid 0); no refills later
        if (tid == 0) {
            asm volatile("fence.proxy.async;" ::: "memory");
            MBARRIER_EXPECT_TX(mbz, 8192);
            cp_bulk(sbase + ZX_OFF_,
                    Zx_all + ((size_t)t * 128 + bx) * 2048, 8192, mbz);
#pragma unroll
            for (int pc = 0; pc < 2; pc++) {
                uint32_t mb = pc ? mb1 : mb0;
                MBARRIER_EXPECT_TX(mb, 65536);
#pragma unroll
                for (int sub = 0; sub < 8; sub++) {
                    int c64 = pc * 8 + sub;
                    cp_bulk(sbase + AST_(pc) + sub * 8192,
                            hin + (size_t)c64 * 8192, 8192, mb);
                }
            }
        }

        float acc[2][4];
#pragma unroll
        for (int nt = 0; nt < 2; nt++)
#pragma unroll
            for (int i = 0; i < 4; i++) acc[nt][i] = 0.0f;

#pragma unroll
        for (int ch = 0; ch < 2; ch++) {
            MBARRIER_WAIT_PARITY(ch ? mb1 : mb0, ph[ch]);
            ph[ch] ^= 1;

#pragma unroll
            for (int sub = 0; sub < 8; sub++) {
                const int c64 = ch * 8 + sub;
                const uint32_t Aa = sbase + AST_(ch) + sub * 8192;
                const uint32_t Bb = sbase + W_ + (uint32_t)c64 * 4096;

#pragma unroll
                for (int ks = 0; ks < 4; ks++) {
                    uint32_t aoff = SWZ((a_r << 7) + (ks * 16 + a_kb) * 2);
                    uint32_t a0, a1, a2, a3;
                    ldsm_x4(a0, a1, a2, a3, Aa + aoff);

                    uint32_t boff = SWZ((b_row << 7) + (ks * 16 + b_kb) * 2);
                    uint32_t b0, b1, b2, b3;
                    ldsm_x4(b0, b1, b2, b3, Bb + boff);

                    mma_f16(acc[0], a0, a1, a2, a3, b0, b1);
                    mma_f16(acc[1], a0, a1, a2, a3, b2, b3);
                }
            }
        }
        __syncthreads();   // all warps done reading stages before Zs overlay

        // stage accumulators to SMEM (overlay A stage 0)
        float* Zs = (float*)(sm + ZS_OFF_);
        {
            const int g  = lane >> 2;
            const int tg = lane & 3;
#pragma unroll
            for (int nt = 0; nt < 2; nt++) {
                int n = wn * 16 + nt * 8 + tg * 2;
                Zs[(m0 + g)     * 32 + n]     = acc[nt][0];
                Zs[(m0 + g)     * 32 + n + 1] = acc[nt][1];
                Zs[(m0 + g + 8) * 32 + n]     = acc[nt][2];
                Zs[(m0 + g + 8) * 32 + n + 1] = acc[nt][3];
            }
        }
        __syncthreads();
        MBARRIER_WAIT_PARITY(mbz, phz);
        phz ^= 1;

        // fused LSTM epilogue: 512 (b, jl) pairs, 2 per thread, c in registers
        const float* zxs = (const float*)(sm + ZX_OFF_);
        float* out_t = out + (size_t)t * BH_;
        char* hout_c = hout + (size_t)hc64 * 8192;
#pragma unroll
        for (int p0 = 0; p0 < 2; p0++) {
            int p  = tid + p0 * 256;
            int b  = p >> 3;
            int jl = p & 7;
            float4 zh  = *(const float4*)&Zs[b * 32 + jl * 4];
            float4 zx4 = *(const float4*)&zxs[b * 32 + jl * 4];

            float f  = sigf(__cosf(zh.x + zx4.x) + s_gb[0 * 8 + jl]);
            float ii = sigf(__cosf(zh.y + zx4.y) + s_gb[1 * 8 + jl]);
            float g  = tanh_fast(__cosf(zh.z + zx4.z) + s_gb[2 * 8 + jl]);
            float o  = sigf(__cosf(zh.w + zx4.w) + s_gb[3 * 8 + jl]);

            float c = f * c_reg[p0] + ii * g;
            c_reg[p0] = c;
            float h = o * tanh_fast(c);

            size_t idx = (size_t)b * H_ + j0 + jl;
            out_t[idx] = h;

            uint32_t hoff = SWZ((uint32_t)(b * 128 + (kcb + jl) * 2));
            *(__half*)(hout_c + hoff) = __float2half(h);

            if (hc_tail && t == T_ - 1) {
                hc_tail[idx] = h;
                hc_tail[(size_t)BH_ + idx] = c;
            }
        }

        // grid barrier (skip after last step)
        if (t + 1 < T_) {
            __syncthreads();
            if (tid == 0) {
                asm volatile("red.release.gpu.add.u32 [%0], 1;" :: "l"(&g_bar) : "memory");
                unsigned target = (unsigned)(t + 1) * 128u;
                unsigned v;
                do {
                    asm volatile("ld.acquire.gpu.u32 %0, [%1];" : "=r"(v) : "l"(&g_bar) : "memory");
                } while (v < target);
            }
            __syncthreads();
        }
    }
}

// ---------------------------------------------------------------------------
extern "C" void kernel_launch(void* const* d_in, const int* in_sizes, int n_in,
                              void* d_out, int out_size)
{
    const float* X   = (const float*)d_in[0];
    const float* Wf  = (const float*)d_in[1];
    const float* bf  = (const float*)d_in[2];
    const float* gbf = (const float*)d_in[3];
    const float* Wi  = (const float*)d_in[4];
    const float* bi  = (const float*)d_in[5];
    const float* gbi = (const float*)d_in[6];
    const float* Wu  = (const float*)d_in[7];
    const float* bu  = (const float*)d_in[8];
    const float* gbu = (const float*)d_in[9];
    const float* Wo  = (const float*)d_in[10];
    const float* bo  = (const float*)d_in[11];
    const float* gbo = (const float*)d_in[12];

    float* out = (float*)d_out;

    float *p_zx;
    __half *p_whf, *p_wxf, *p_xf;
    char* p_hf;
    unsigned* p_bar;
    cudaGetSymbolAddress((void**)&p_zx,  g_zx);
    cudaGetSymbolAddress((void**)&p_whf, g_whf);
    cudaGetSymbolAddress((void**)&p_wxf, g_wxf);
    cudaGetSymbolAddress((void**)&p_xf,  g_xf);
    cudaGetSymbolAddress((void**)&p_hf,  g_hf);
    cudaGetSymbolAddress((void**)&p_bar, g_bar);

    cudaFuncSetAttribute(lstm_persist, cudaFuncAttributeMaxDynamicSharedMemorySize, SMEM_DYN_);
    cudaFuncSetAttribute(gemm_tc, cudaFuncAttributeMaxDynamicSharedMemorySize, GSMEM_);

    // reset initial h buffer (parity 0) and the barrier counter
    cudaMemsetAsync(p_hf, 0, HBUF_STRIDE_);
    cudaMemsetAsync(p_bar, 0, sizeof(unsigned));

    // Phase 0: weight/input conversion (all single fp16)
    conv_w<<<(NG_ * H_) / 256, 256>>>(Wf, Wi, Wu, Wo, p_whf);
    conv_wx<<<(NG_ * D_) / 256, 256>>>(Wf, Wi, Wu, Wo, p_wxf);
    conv_x<<<(M_ * D_) / 256, 256>>>(X, p_xf);

    // Phase 1: all-timestep input projection (+bias), single fp16 GEMM
    dim3 g1(NG_ / 128, M_ / 128);
    gemm_tc<<<g1, 256, GSMEM_>>>(p_xf, p_wxf, bf, bi, bu, bo, p_zx);

    // Phase 2: persistent fused recurrence (all 256 steps in one kernel)
    const size_t TBH = (size_t)T_ * B_ * H_;
    const bool tails = out_size >= (int)(TBH + 2 * (size_t)BH_);
    lstm_persist<<<128, 256, SMEM_DYN_>>>(
        p_zx, p_whf, p_hf,
        gbf, gbi, gbu, gbo,
        out, tails ? out + TBH : nullptr);
}